// round 12
// baseline (speedup 1.0000x reference)
#include <cuda_runtime.h>
#include <cuda_bf16.h>
#include <cuda_fp16.h>
#include <cstdint>
#include <cstddef>

#define B_  2
#define T_  2048
#define C_  2048
#define HQ  32
#define HKV 8
#define HD  64
#define M_  (B_*T_)      // 4096
#define KVC (HKV*HD)     // 512

// ------------------------- scratch (no cudaMalloc) -------------------------
// Projection-GEMM operands: fp16, blocked [rowBlk][kBlk][128x32], swizzled.
__device__ __half g_xh[(size_t)M_*C_];
__device__ __half g_wqh[(size_t)C_*C_];
__device__ __half g_wkh[(size_t)KVC*C_];
__device__ __half g_wvh[(size_t)KVC*C_];
__device__ __half g_woh[(size_t)C_*C_];
__device__ __half g_oh[(size_t)M_*C_];
// Attention operands: bf16 hi/lo (unchanged numerics).
__device__ __nv_bfloat16 g_qh[(size_t)M_*C_],  g_ql[(size_t)M_*C_];
__device__ __nv_bfloat16 g_kh[(size_t)M_*KVC], g_kl[(size_t)M_*KVC];
__device__ __nv_bfloat16 g_vh[(size_t)M_*KVC], g_vl[(size_t)M_*KVC];

// ------------------------- helpers -----------------------------------------
__device__ __forceinline__ uint32_t s2u(const void* p) {
    uint32_t a;
    asm("{ .reg .u64 t; cvta.to.shared.u64 t, %1; cvt.u32.u64 %0, t; }"
        : "=r"(a) : "l"(p));
    return a;
}
__device__ __forceinline__ void bulk_ld(uint32_t dst, const void* src,
                                        uint32_t bytes, uint32_t mbar) {
    asm volatile(
        "cp.async.bulk.shared::cluster.global.mbarrier::complete_tx::bytes "
        "[%0], [%1], %2, [%3];"
        :: "r"(dst), "l"(src), "r"(bytes), "r"(mbar) : "memory");
}
__device__ __forceinline__ void mbar_init(uint32_t mbar, uint32_t cnt) {
    asm volatile("mbarrier.init.shared.b64 [%0], %1;" :: "r"(mbar), "r"(cnt) : "memory");
}
__device__ __forceinline__ void mbar_expect(uint32_t mbar, uint32_t tx) {
    asm volatile("mbarrier.arrive.expect_tx.shared.b64 _, [%0], %1;"
                 :: "r"(mbar), "r"(tx) : "memory");
}
__device__ __forceinline__ void mbar_arrive(uint32_t mbar) {
    asm volatile("mbarrier.arrive.shared.b64 _, [%0];" :: "r"(mbar) : "memory");
}
__device__ __forceinline__ void wait_parity(uint32_t mbar, uint32_t phase) {
    asm volatile(
        "{ .reg .pred P1;\n"
        "WL%=:\n"
        " mbarrier.try_wait.parity.acquire.cta.shared::cta.b64 P1, [%0], %1, 0x989680;\n"
        " @P1 bra.uni WD%=;\n"
        " bra.uni WL%=;\n"
        "WD%=:\n }"
        :: "r"(mbar), "r"(phase) : "memory");
}
#define LDM4(r0,r1,r2,r3,addr) \
    asm volatile("ldmatrix.sync.aligned.m8n8.x4.shared.b16 {%0,%1,%2,%3}, [%4];" \
                 : "=r"(r0),"=r"(r1),"=r"(r2),"=r"(r3) : "r"(addr))
#define LDM4T(r0,r1,r2,r3,addr) \
    asm volatile("ldmatrix.sync.aligned.m8n8.x4.trans.shared.b16 {%0,%1,%2,%3}, [%4];" \
                 : "=r"(r0),"=r"(r1),"=r"(r2),"=r"(r3) : "r"(addr))
// bf16 mma (attention)
#define MMAB(d,a,b0,b1) \
    asm volatile("mma.sync.aligned.m16n8k16.row.col.f32.bf16.bf16.f32 " \
                 "{%0,%1,%2,%3},{%4,%5,%6,%7},{%8,%9},{%0,%1,%2,%3};" \
                 : "+f"((d)[0]),"+f"((d)[1]),"+f"((d)[2]),"+f"((d)[3]) \
                 : "r"((a)[0]),"r"((a)[1]),"r"((a)[2]),"r"((a)[3]), \
                   "r"(b0),"r"(b1))
// fp16 mma (projection GEMMs)
#define MMAH(d,a,b0,b1) \
    asm volatile("mma.sync.aligned.m16n8k16.row.col.f32.f16.f16.f32 " \
                 "{%0,%1,%2,%3},{%4,%5,%6,%7},{%8,%9},{%0,%1,%2,%3};" \
                 : "+f"((d)[0]),"+f"((d)[1]),"+f"((d)[2]),"+f"((d)[3]) \
                 : "r"((a)[0]),"r"((a)[1]),"r"((a)[2]),"r"((a)[3]), \
                   "r"(b0),"r"(b1))

__device__ __forceinline__ float ex2f(float x) {
    float r; asm("ex2.approx.f32 %0,%1;" : "=f"(r) : "f"(x)); return r;
}
__device__ __forceinline__ uint32_t packbf(float hi, float lo) {
    uint32_t r; asm("cvt.rn.bf16x2.f32 %0,%1,%2;" : "=r"(r) : "f"(hi), "f"(lo));
    return r;
}
__device__ __forceinline__ float bflo(uint32_t v) { return __uint_as_float(v << 16); }
__device__ __forceinline__ float bfhi(uint32_t v) { return __uint_as_float(v & 0xffff0000u); }

// ------------------- fused fp32 -> blocked swizzled fp16 --------------------
struct SplitArgs {
    const float* src[5];
    __half* hi[5];
    int nchunk[5];
};
__global__ __launch_bounds__(256)
void split_all(SplitArgs a) {
    const int m = blockIdx.y;
    const int i = blockIdx.x * 256 + threadIdx.x;
    if (i >= a.nchunk[m]) return;
    const float4* p = (const float4*)a.src[m] + (size_t)i * 2;
    float4 va = p[0], vb = p[1];
    float f[8] = {va.x, va.y, va.z, va.w, vb.x, vb.y, vb.z, vb.w};
    __half h[8];
#pragma unroll
    for (int j = 0; j < 8; j++) h[j] = __float2half_rn(f[j]);
    const int e = i * 8;
    const int r = e >> 11, k = e & 2047;
    const int rr = r & 127, ch = (k & 31) >> 3;
    const size_t off = ((size_t)((r >> 7) * 64 + (k >> 5)) << 13)
                     + (rr << 6) + (((ch + (rr >> 1)) & 3) << 4);
    *(uint4*)((char*)a.hi[m] + off) = *(uint4*)h;
}

// ---------------------------------------------------------------------------
// fp16 GEMM mainloop: 256x128 tile, 8 warps (4x2), warp tile 64x64, 1 MMA/MAC.
// 5-stage bulk ring, stage = {Ah0, Ah1, Bh} = 24KB.
// ---------------------------------------------------------------------------
#define GSTG 24576u
#define NSTG 5
__device__ __forceinline__ void gemm_core256_f16(
        uint32_t sb, int tid, int lane, int wm, int wn,
        const char* Ath, const char* Bth, float acc[4][8][4]) {
    const uint32_t fb = sb + NSTG * GSTG;
    if (tid == 0) {
#pragma unroll
        for (int i = 0; i < NSTG; i++) mbar_init(fb + i * 8, 1);
        asm volatile("fence.mbarrier_init.release.cluster;" ::: "memory");
    }
    __syncthreads();
    auto gissue = [&](int s_) {
        int slot = s_ % NSTG;
        uint32_t mb  = fb + (slot << 3);
        uint32_t dst = sb + (uint32_t)slot * GSTG;
        size_t   off = (size_t)s_ * 8192;
        mbar_expect(mb, GSTG);
        bulk_ld(dst,           Ath + off,          8192, mb);
        bulk_ld(dst + 8192u,   Ath + 524288 + off, 8192, mb);
        bulk_ld(dst + 16384u,  Bth + off,          8192, mb);
    };
    if (tid == 0) { gissue(0); gissue(1); gissue(2); gissue(3); }

    const int ra = wm * 64 + (lane & 7) + ((lane >> 3) & 1) * 8;
    const int ca = (lane >> 4) & 1;
    const int rb2 = wn * 64 + (lane & 7) + ((lane >> 4) & 1) * 8;
    const int cb = (lane >> 3) & 1;

    for (int s = 0; s < 64; s++) {
        int slot = s % NSTG;
        wait_parity(fb + (slot << 3), (uint32_t)((s / NSTG) & 1));
        const uint32_t bufA = sb + (uint32_t)slot * GSTG;
        const uint32_t bufB = bufA + 16384u;
#pragma unroll
        for (int ks = 0; ks < 2; ks++) {
            uint32_t ah[4][4], bh[8][2];
#pragma unroll
            for (int mi = 0; mi < 4; mi++) {
                int r = ra + mi * 16;
                int c = ks * 2 + ca;
                uint32_t ad = bufA + r * 64 + (((c + (r >> 1)) & 3) << 4);
                LDM4(ah[mi][0], ah[mi][1], ah[mi][2], ah[mi][3], ad);
            }
#pragma unroll
            for (int np = 0; np < 4; np++) {
                int r = rb2 + np * 16;
                int c = ks * 2 + cb;
                uint32_t bd = bufB + r * 64 + (((c + (r >> 1)) & 3) << 4);
                LDM4(bh[2*np][0], bh[2*np][1], bh[2*np+1][0], bh[2*np+1][1], bd);
            }
#pragma unroll
            for (int mi = 0; mi < 4; mi++)
#pragma unroll
                for (int ni = 0; ni < 8; ni++)
                    MMAH(acc[mi][ni], ah[mi], bh[ni][0], bh[ni][1]);
        }
        __syncthreads();
        if (tid == 0 && s + 4 < 64) gissue(s + 4);
    }
}

// ---------------------------------------------------------------------------
// Fused Q/K/V projection GEMM (fp16), epilogue -> attention bf16 hi/lo tiles.
// grid (24, 16): bx 0-15 = Q, 16-19 = K, 20-23 = V; by = 256-row block.
// ---------------------------------------------------------------------------
__global__ __launch_bounds__(256, 1)
void gemm_qkv(const __half* __restrict__ xh,
              const __half* __restrict__ wqh, const __half* __restrict__ wkh,
              const __half* __restrict__ wvh,
              __nv_bfloat16* __restrict__ qh, __nv_bfloat16* __restrict__ ql,
              __nv_bfloat16* __restrict__ kh, __nv_bfloat16* __restrict__ kl,
              __nv_bfloat16* __restrict__ vh, __nv_bfloat16* __restrict__ vl) {
    extern __shared__ __align__(1024) char smem[];
    const uint32_t sb = s2u(smem);
    const int tid = threadIdx.x, lane = tid & 31, wid = tid >> 5;
    const int wm = wid >> 1, wn = wid & 1;
    const int bx = blockIdx.x, br = blockIdx.y * 256;

    int sel, bc;
    const __half* Bh;
    __nv_bfloat16 *Dh, *Dl;
    if (bx < 16)      { sel = 0; bc = bx * 128;        Bh = wqh; Dh = qh; Dl = ql; }
    else if (bx < 20) { sel = 1; bc = (bx - 16) * 128; Bh = wkh; Dh = kh; Dl = kl; }
    else              { sel = 2; bc = (bx - 20) * 128; Bh = wvh; Dh = vh; Dl = vl; }

    float acc[4][8][4];
#pragma unroll
    for (int mi = 0; mi < 4; mi++)
#pragma unroll
        for (int ni = 0; ni < 8; ni++)
#pragma unroll
            for (int r = 0; r < 4; r++) acc[mi][ni][r] = 0.f;

    gemm_core256_f16(sb, tid, lane, wm, wn,
                     (const char*)xh + (size_t)(br >> 7) * 524288,
                     (const char*)Bh + (size_t)(bc >> 7) * 524288, acc);

    const int g = lane >> 2, t4 = lane & 3;
    const int nheads16 = (sel == 0) ? 32 * 16 : 8 * 16;
#pragma unroll
    for (int mi = 0; mi < 4; mi++) {
        int row = br + wm * 64 + mi * 16 + g;
        int b = row >> 11, t = row & 2047;
        int rb2 = t >> 7, rr = t & 127;
#pragma unroll
        for (int ni = 0; ni < 8; ni++) {
            int col = bc + wn * 64 + ni * 8 + t4 * 2;
            int hh = col >> 6, c = col & 63;
            size_t tile = (size_t)b * nheads16 + (size_t)hh * 16 + rb2;
            uint32_t h01 = packbf(acc[mi][ni][1], acc[mi][ni][0]);
            uint32_t l01 = packbf(acc[mi][ni][1] - bfhi(h01), acc[mi][ni][0] - bflo(h01));
            uint32_t h23 = packbf(acc[mi][ni][3], acc[mi][ni][2]);
            uint32_t l23 = packbf(acc[mi][ni][3] - bfhi(h23), acc[mi][ni][2] - bflo(h23));
            size_t o0 = (tile << 14) + rr * 128
                      + ((((c >> 3) + (rr & 7)) & 7) << 4) + (c & 7) * 2;
            int rr8 = rr + 8;
            size_t o1 = (tile << 14) + rr8 * 128
                      + ((((c >> 3) + (rr8 & 7)) & 7) << 4) + (c & 7) * 2;
            *(uint32_t*)((char*)Dh + o0) = h01;
            *(uint32_t*)((char*)Dl + o0) = l01;
            *(uint32_t*)((char*)Dh + o1) = h23;
            *(uint32_t*)((char*)Dl + o1) = l23;
        }
    }
}

// ---------------------------------------------------------------------------
// Output projection GEMM (fp16): out fp32 row-major.
// ---------------------------------------------------------------------------
__global__ __launch_bounds__(256, 1)
void gemm_o(const __half* __restrict__ oh, const __half* __restrict__ woh,
            float* __restrict__ out) {
    extern __shared__ __align__(1024) char smem[];
    const uint32_t sb = s2u(smem);
    const int tid = threadIdx.x, lane = tid & 31, wid = tid >> 5;
    const int wm = wid >> 1, wn = wid & 1;
    const int br = blockIdx.y * 256, bc = blockIdx.x * 128;

    float acc[4][8][4];
#pragma unroll
    for (int mi = 0; mi < 4; mi++)
#pragma unroll
        for (int ni = 0; ni < 8; ni++)
#pragma unroll
            for (int r = 0; r < 4; r++) acc[mi][ni][r] = 0.f;

    gemm_core256_f16(sb, tid, lane, wm, wn,
                     (const char*)oh + (size_t)(br >> 7) * 524288,
                     (const char*)woh + (size_t)(bc >> 7) * 524288, acc);

    const int g = lane >> 2, t4 = lane & 3;
#pragma unroll
    for (int mi = 0; mi < 4; mi++)
#pragma unroll
        for (int ni = 0; ni < 8; ni++) {
            int row = br + wm * 64 + mi * 16 + g;
            int col = bc + wn * 64 + ni * 8 + t4 * 2;
            *(float2*)(out + (size_t)row * C_ + col) =
                make_float2(acc[mi][ni][0], acc[mi][ni][1]);
            *(float2*)(out + (size_t)(row + 8) * C_ + col) =
                make_float2(acc[mi][ni][2], acc[mi][ni][3]);
        }
}

// ---------------------------------------------------------------------------
// Flash attention (mma.sync bf16x3, 3-term QK and PV) — numerics unchanged.
// 3-stage bulk KV ring, warp-drift sync + LPT ordering.
// Output: fp16 single (gemm_o's A operand), GEMM-A blocked layout.
// ---------------------------------------------------------------------------
__global__ __launch_bounds__(256, 1)
void attn_mma(const __nv_bfloat16* __restrict__ Qh, const __nv_bfloat16* __restrict__ Ql,
              const __nv_bfloat16* __restrict__ Kh, const __nv_bfloat16* __restrict__ Kl,
              const __nv_bfloat16* __restrict__ Vh, const __nv_bfloat16* __restrict__ Vl,
              __half* __restrict__ Oh) {
    extern __shared__ __align__(1024) char smem[];
    const uint32_t sb = s2u(smem);
    const uint32_t fb = sb + 229376u;
    const int tid = threadIdx.x, lane = tid & 31, wid = tid >> 5;
    const int qb = 15 - blockIdx.x;              // LPT: heavy blocks first
    const int bh = blockIdx.y;
    const int b = bh >> 5, h = bh & 31, kvh = h >> 2;
    const int g = lane >> 2, t4 = lane & 3;
    const float F = 0.125f * 1.44269504089f;

    if (tid == 0) {
        mbar_init(fb, 1);
        mbar_init(fb + 8, 1);  mbar_init(fb + 16, 1); mbar_init(fb + 24, 1);
        mbar_init(fb + 32, 8); mbar_init(fb + 40, 8); mbar_init(fb + 48, 8);
        asm volatile("fence.mbarrier_init.release.cluster;" ::: "memory");
    }
    __syncthreads();

    const size_t qtb = ((size_t)(b * 32 + h) * 16 + qb) << 14;
    auto issueKV = [&](int kb) {
        int slot = kb % 3;
        uint32_t mb  = fb + 8 + (slot << 3);
        uint32_t dst = sb + 32768u + (uint32_t)slot * 65536u;
        size_t toff  = ((size_t)(b * 8 + kvh) * 16 + kb) << 14;
        mbar_expect(mb, 65536u);
        bulk_ld(dst,           (const char*)Kh + toff, 16384, mb);
        bulk_ld(dst + 16384u,  (const char*)Kl + toff, 16384, mb);
        bulk_ld(dst + 32768u,  (const char*)Vh + toff, 16384, mb);
        bulk_ld(dst + 49152u,  (const char*)Vl + toff, 16384, mb);
    };
    if (tid == 0) {
        mbar_expect(fb, 32768u);
        bulk_ld(sb,           (const char*)Qh + qtb, 16384, fb);
        bulk_ld(sb + 16384u,  (const char*)Ql + qtb, 16384, fb);
        issueKV(0);
        if (qb >= 1) issueKV(1);
    }

    wait_parity(fb, 0);
    uint32_t qfh[4][4], qfl[4][4];
    {
        int r = 16 * wid + (lane & 7) + ((lane >> 3) & 1) * 8;
#pragma unroll
        for (int ki = 0; ki < 4; ki++) {
            int c8 = ki * 2 + ((lane >> 4) & 1);
            uint32_t ad = sb + r * 128 + (((c8 + (r & 7)) & 7) << 4);
            LDM4(qfh[ki][0], qfh[ki][1], qfh[ki][2], qfh[ki][3], ad);
            LDM4(qfl[ki][0], qfl[ki][1], qfl[ki][2], qfl[ki][3], ad + 16384u);
        }
    }

    float oacc[8][4];
#pragma unroll
    for (int i = 0; i < 8; i++)
#pragma unroll
        for (int j = 0; j < 4; j++) oacc[i][j] = 0.f;
    float m0 = -1e30f, m1 = -1e30f, l0 = 0.f, l1 = 0.f;

    for (int kb = 0; kb <= qb; kb++) {
        if (tid == 0) {
            int n = kb + 2;
            if (n <= qb) {
                if (n >= 3)
                    wait_parity(fb + 32 + ((n % 3) << 3), (uint32_t)(((n - 3) / 3) & 1));
                issueKV(n);
            }
        }
        wait_parity(fb + 8 + ((kb % 3) << 3), (uint32_t)((kb / 3) & 1));
        const uint32_t base = sb + 32768u + (uint32_t)(kb % 3) * 65536u;

        // ---- S = Q K^T (bf16x3)
        float s[16][4];
#pragma unroll
        for (int i = 0; i < 16; i++)
#pragma unroll
            for (int j = 0; j < 4; j++) s[i][j] = 0.f;
        {
            int rk = (lane & 7) + ((lane >> 3) & 1) * 8;
#pragma unroll
            for (int n2 = 0; n2 < 8; n2++) {
                int row = n2 * 16 + rk;
#pragma unroll
                for (int ki = 0; ki < 4; ki++) {
                    int c8 = ki * 2 + ((lane >> 4) & 1);
                    uint32_t ad = base + row * 128 + (((c8 + (row & 7)) & 7) << 4);
                    uint32_t k0, k1, k2, k3, e0, e1, e2, e3;
                    LDM4(k0, k1, k2, k3, ad);
                    LDM4(e0, e1, e2, e3, ad + 16384u);
                    MMAB(s[2*n2],   qfh[ki], k0, k2);
                    MMAB(s[2*n2],   qfh[ki], e0, e2);
                    MMAB(s[2*n2],   qfl[ki], k0, k2);
                    MMAB(s[2*n2+1], qfh[ki], k1, k3);
                    MMAB(s[2*n2+1], qfh[ki], e1, e3);
                    MMAB(s[2*n2+1], qfl[ki], k1, k3);
                }
            }
        }
        if (kb == qb) {
            int rl = 16 * wid + g;
#pragma unroll
            for (int ni = 0; ni < 16; ni++) {
                int c = ni * 8 + t4 * 2;
                if (c     > rl)     s[ni][0] = -1e30f;
                if (c + 1 > rl)     s[ni][1] = -1e30f;
                if (c     > rl + 8) s[ni][2] = -1e30f;
                if (c + 1 > rl + 8) s[ni][3] = -1e30f;
            }
        }
        // ---- online softmax
        float mx0 = -1e30f, mx1 = -1e30f;
#pragma unroll
        for (int ni = 0; ni < 16; ni++) {
            mx0 = fmaxf(mx0, fmaxf(s[ni][0], s[ni][1]));
            mx1 = fmaxf(mx1, fmaxf(s[ni][2], s[ni][3]));
        }
        mx0 = fmaxf(mx0, __shfl_xor_sync(0xffffffffu, mx0, 1));
        mx0 = fmaxf(mx0, __shfl_xor_sync(0xffffffffu, mx0, 2));
        mx1 = fmaxf(mx1, __shfl_xor_sync(0xffffffffu, mx1, 1));
        mx1 = fmaxf(mx1, __shfl_xor_sync(0xffffffffu, mx1, 2));
        float mn0 = fmaxf(m0, mx0 * F), mn1 = fmaxf(m1, mx1 * F);
        float a0 = ex2f(m0 - mn0), a1 = ex2f(m1 - mn1);
        l0 *= a0; l1 *= a1;
#pragma unroll
        for (int ni = 0; ni < 8; ni++) {
            oacc[ni][0] *= a0; oacc[ni][1] *= a0;
            oacc[ni][2] *= a1; oacc[ni][3] *= a1;
        }
        m0 = mn0; m1 = mn1;

        uint32_t pa[16], pb[16], la[16], lb[16];
#pragma unroll
        for (int ni = 0; ni < 16; ni++) {
            float p0 = ex2f(fmaf(s[ni][0], F, -mn0));
            float p1 = ex2f(fmaf(s[ni][1], F, -mn0));
            float p2 = ex2f(fmaf(s[ni][2], F, -mn1));
            float p3 = ex2f(fmaf(s[ni][3], F, -mn1));
            l0 += p0 + p1; l1 += p2 + p3;
            uint32_t hA = packbf(p1, p0), hB = packbf(p3, p2);
            pa[ni] = hA; pb[ni] = hB;
            la[ni] = packbf(p1 - bfhi(hA), p0 - bflo(hA));
            lb[ni] = packbf(p3 - bfhi(hB), p2 - bflo(hB));
        }

        // ---- O += P V (bf16x3)
        {
            const uint32_t baseV = base + 32768u;
            int rv = (lane & 7) + ((lane >> 3) & 1) * 8;
#pragma unroll
            for (int ki = 0; ki < 8; ki++) {
                uint32_t ah[4] = {pa[2*ki], pb[2*ki], pa[2*ki+1], pb[2*ki+1]};
                uint32_t al[4] = {la[2*ki], lb[2*ki], la[2*ki+1], lb[2*ki+1]};
                int row = ki * 16 + rv;
#pragma unroll
                for (int dv = 0; dv < 4; dv++) {
                    int c8 = dv * 2 + ((lane >> 4) & 1);
                    uint32_t ad = baseV + row * 128 + (((c8 + (row & 7)) & 7) << 4);
                    uint32_t v0, v1, v2, v3, w0, w1, w2, w3;
                    LDM4T(v0, v1, v2, v3, ad);
                    LDM4T(w0, w1, w2, w3, ad + 16384u);
                    MMAB(oacc[2*dv],   ah, v0, v1);
                    MMAB(oacc[2*dv],   ah, w0, w1);
                    MMAB(oacc[2*dv],   al, v0, v1);
                    MMAB(oacc[2*dv+1], ah, v2, v3);
                    MMAB(oacc[2*dv+1], ah, w2, w3);
                    MMAB(oacc[2*dv+1], al, v2, v3);
                }
            }
        }
        if (lane == 0) mbar_arrive(fb + 32 + ((kb % 3) << 3));
    }

    // ---- epilogue: write O as fp16 in GEMM-A blocked layout
    l0 += __shfl_xor_sync(0xffffffffu, l0, 1);
    l0 += __shfl_xor_sync(0xffffffffu, l0, 2);
    l1 += __shfl_xor_sync(0xffffffffu, l1, 1);
    l1 += __shfl_xor_sync(0xffffffffu, l1, 2);
    const float i0 = 1.f / l0, i1 = 1.f / l1;
    const int rr0 = 16 * wid + g;
    const int rowg = b * 2048 + qb * 128 + rr0;
    const int rowBlk = rowg >> 7;
#pragma unroll
    for (int ni = 0; ni < 8; ni++) {
        int cg = h * 64 + ni * 8 + t4 * 2;
        int tile = rowBlk * 64 + (cg >> 5);
        int cc = cg & 31, ch = cc >> 3;
        __half2 h2a = __floats2half2_rn(oacc[ni][0] * i0, oacc[ni][1] * i0);
        __half2 h2b = __floats2half2_rn(oacc[ni][2] * i1, oacc[ni][3] * i1);
        int rr1 = rr0 + 8;
        size_t o0 = ((size_t)tile << 13) + rr0 * 64 + (((ch + (rr0 >> 1)) & 3) << 4) + (cc & 7) * 2;
        size_t o1 = ((size_t)tile << 13) + rr1 * 64 + (((ch + (rr1 >> 1)) & 3) << 4) + (cc & 7) * 2;
        *(__half2*)((char*)Oh + o0) = h2a;
        *(__half2*)((char*)Oh + o1) = h2b;
    }
}

// ---------------------------------------------------------------------------
extern "C" void kernel_launch(void* const* d_in, const int* in_sizes, int n_in,
                              void* d_out, int out_size) {
    const float* x  = (const float*)d_in[0];
    const float* wq = (const float*)d_in[1];
    const float* wk = (const float*)d_in[2];
    const float* wv = (const float*)d_in[3];
    const float* wo = (const float*)d_in[4];
    float* out = (float*)d_out;

    __half *xh, *wqh, *wkh, *wvh, *woh, *oh;
    __nv_bfloat16 *qh, *ql, *kh, *kl, *vh, *vl;
    cudaGetSymbolAddress((void**)&xh, g_xh);
    cudaGetSymbolAddress((void**)&wqh, g_wqh);
    cudaGetSymbolAddress((void**)&wkh, g_wkh);
    cudaGetSymbolAddress((void**)&wvh, g_wvh);
    cudaGetSymbolAddress((void**)&woh, g_woh);
    cudaGetSymbolAddress((void**)&oh, g_oh);
    cudaGetSymbolAddress((void**)&qh, g_qh);   cudaGetSymbolAddress((void**)&ql, g_ql);
    cudaGetSymbolAddress((void**)&kh, g_kh);   cudaGetSymbolAddress((void**)&kl, g_kl);
    cudaGetSymbolAddress((void**)&vh, g_vh);   cudaGetSymbolAddress((void**)&vl, g_vl);

    const int GS = NSTG * 24576 + 40;   // 122920
    const int AS = 229376 + 56;         // 229432
    cudaFuncSetAttribute(gemm_qkv, cudaFuncAttributeMaxDynamicSharedMemorySize, GS);
    cudaFuncSetAttribute(gemm_o,   cudaFuncAttributeMaxDynamicSharedMemorySize, GS);
    cudaFuncSetAttribute(attn_mma, cudaFuncAttributeMaxDynamicSharedMemorySize, AS);

    SplitArgs sa;
    sa.src[0] = x;  sa.hi[0] = xh;  sa.nchunk[0] = M_ * C_ / 8;
    sa.src[1] = wq; sa.hi[1] = wqh; sa.nchunk[1] = C_ * C_ / 8;
    sa.src[2] = wk; sa.hi[2] = wkh; sa.nchunk[2] = KVC * C_ / 8;
    sa.src[3] = wv; sa.hi[3] = wvh; sa.nchunk[3] = KVC * C_ / 8;
    sa.src[4] = wo; sa.hi[4] = woh; sa.nchunk[4] = C_ * C_ / 8;
    split_all<<<dim3((M_ * C_ / 8 + 255) / 256, 5), 256>>>(sa);

    gemm_qkv<<<dim3(24, 16), 256, GS>>>(xh, wqh, wkh, wvh,
                                        qh, ql, kh, kl, vh, vl);
    attn_mma<<<dim3(T_ / 128, B_ * HQ), 256, AS>>>(qh, ql, kh, kl, vh, vl, oh);
    gemm_o<<<dim3(16, 16), 256, GS>>>(oh, woh, out);
}

// round 13
// speedup vs baseline: 1.1649x; 1.1649x over previous
#include <cuda_runtime.h>
#include <cuda_bf16.h>
#include <cuda_fp16.h>
#include <cstdint>
#include <cstddef>

#define B_  2
#define T_  2048
#define C_  2048
#define HQ  32
#define HKV 8
#define HD  64
#define M_  (B_*T_)      // 4096
#define KVC (HKV*HD)     // 512

// ------------------------- scratch (no cudaMalloc) -------------------------
// bf16 hi/lo (projection inputs + attention operands)
__device__ __nv_bfloat16 g_xh[(size_t)M_*C_],  g_xl[(size_t)M_*C_];
__device__ __nv_bfloat16 g_wqh[(size_t)C_*C_], g_wql[(size_t)C_*C_];
__device__ __nv_bfloat16 g_wkh[(size_t)KVC*C_],g_wkl[(size_t)KVC*C_];
__device__ __nv_bfloat16 g_wvh[(size_t)KVC*C_],g_wvl[(size_t)KVC*C_];
__device__ __nv_bfloat16 g_qh[(size_t)M_*C_],  g_ql[(size_t)M_*C_];
__device__ __nv_bfloat16 g_kh[(size_t)M_*KVC], g_kl[(size_t)M_*KVC];
__device__ __nv_bfloat16 g_vh[(size_t)M_*KVC], g_vl[(size_t)M_*KVC];
// fp16 (output-projection operands)
__device__ __half g_woh[(size_t)C_*C_];
__device__ __half g_oh[(size_t)M_*C_];

// ------------------------- helpers -----------------------------------------
__device__ __forceinline__ uint32_t s2u(const void* p) {
    uint32_t a;
    asm("{ .reg .u64 t; cvta.to.shared.u64 t, %1; cvt.u32.u64 %0, t; }"
        : "=r"(a) : "l"(p));
    return a;
}
__device__ __forceinline__ void bulk_ld(uint32_t dst, const void* src,
                                        uint32_t bytes, uint32_t mbar) {
    asm volatile(
        "cp.async.bulk.shared::cluster.global.mbarrier::complete_tx::bytes "
        "[%0], [%1], %2, [%3];"
        :: "r"(dst), "l"(src), "r"(bytes), "r"(mbar) : "memory");
}
__device__ __forceinline__ void mbar_init(uint32_t mbar, uint32_t cnt) {
    asm volatile("mbarrier.init.shared.b64 [%0], %1;" :: "r"(mbar), "r"(cnt) : "memory");
}
__device__ __forceinline__ void mbar_expect(uint32_t mbar, uint32_t tx) {
    asm volatile("mbarrier.arrive.expect_tx.shared.b64 _, [%0], %1;"
                 :: "r"(mbar), "r"(tx) : "memory");
}
__device__ __forceinline__ void mbar_arrive(uint32_t mbar) {
    asm volatile("mbarrier.arrive.shared.b64 _, [%0];" :: "r"(mbar) : "memory");
}
__device__ __forceinline__ void wait_parity(uint32_t mbar, uint32_t phase) {
    asm volatile(
        "{ .reg .pred P1;\n"
        "WL%=:\n"
        " mbarrier.try_wait.parity.acquire.cta.shared::cta.b64 P1, [%0], %1, 0x989680;\n"
        " @P1 bra.uni WD%=;\n"
        " bra.uni WL%=;\n"
        "WD%=:\n }"
        :: "r"(mbar), "r"(phase) : "memory");
}
#define LDM4(r0,r1,r2,r3,addr) \
    asm volatile("ldmatrix.sync.aligned.m8n8.x4.shared.b16 {%0,%1,%2,%3}, [%4];" \
                 : "=r"(r0),"=r"(r1),"=r"(r2),"=r"(r3) : "r"(addr))
#define LDM4T(r0,r1,r2,r3,addr) \
    asm volatile("ldmatrix.sync.aligned.m8n8.x4.trans.shared.b16 {%0,%1,%2,%3}, [%4];" \
                 : "=r"(r0),"=r"(r1),"=r"(r2),"=r"(r3) : "r"(addr))
#define MMA(d,a,b) \
    asm volatile("mma.sync.aligned.m16n8k16.row.col.f32.bf16.bf16.f32 " \
                 "{%0,%1,%2,%3},{%4,%5,%6,%7},{%8,%9},{%0,%1,%2,%3};" \
                 : "+f"((d)[0]),"+f"((d)[1]),"+f"((d)[2]),"+f"((d)[3]) \
                 : "r"((a)[0]),"r"((a)[1]),"r"((a)[2]),"r"((a)[3]), \
                   "r"((b)[0]),"r"((b)[1]))
#define MMAB(d,a,b0,b1) \
    asm volatile("mma.sync.aligned.m16n8k16.row.col.f32.bf16.bf16.f32 " \
                 "{%0,%1,%2,%3},{%4,%5,%6,%7},{%8,%9},{%0,%1,%2,%3};" \
                 : "+f"((d)[0]),"+f"((d)[1]),"+f"((d)[2]),"+f"((d)[3]) \
                 : "r"((a)[0]),"r"((a)[1]),"r"((a)[2]),"r"((a)[3]), \
                   "r"(b0),"r"(b1))
#define MMAH(d,a,b0,b1) \
    asm volatile("mma.sync.aligned.m16n8k16.row.col.f32.f16.f16.f32 " \
                 "{%0,%1,%2,%3},{%4,%5,%6,%7},{%8,%9},{%0,%1,%2,%3};" \
                 : "+f"((d)[0]),"+f"((d)[1]),"+f"((d)[2]),"+f"((d)[3]) \
                 : "r"((a)[0]),"r"((a)[1]),"r"((a)[2]),"r"((a)[3]), \
                   "r"(b0),"r"(b1))

__device__ __forceinline__ float ex2f(float x) {
    float r; asm("ex2.approx.f32 %0,%1;" : "=f"(r) : "f"(x)); return r;
}
__device__ __forceinline__ uint32_t packbf(float hi, float lo) {
    uint32_t r; asm("cvt.rn.bf16x2.f32 %0,%1,%2;" : "=r"(r) : "f"(hi), "f"(lo));
    return r;
}
__device__ __forceinline__ float bflo(uint32_t v) { return __uint_as_float(v << 16); }
__device__ __forceinline__ float bfhi(uint32_t v) { return __uint_as_float(v & 0xffff0000u); }

// ------------- fused fp32 -> blocked swizzled bf16 hi/lo (x, wq, wk, wv) ----
struct SplitArgs {
    const float* src[4];
    __nv_bfloat16* hi[4];
    __nv_bfloat16* lo[4];
    int nchunk[4];
};
__global__ __launch_bounds__(256)
void split_all(SplitArgs a) {
    const int m = blockIdx.y;
    const int i = blockIdx.x * 256 + threadIdx.x;
    if (i >= a.nchunk[m]) return;
    const float4* p = (const float4*)a.src[m] + (size_t)i * 2;
    float4 va = p[0], vb = p[1];
    float f[8] = {va.x, va.y, va.z, va.w, vb.x, vb.y, vb.z, vb.w};
    __nv_bfloat16 h[8], l[8];
#pragma unroll
    for (int j = 0; j < 8; j++) {
        h[j] = __float2bfloat16(f[j]);
        l[j] = __float2bfloat16(f[j] - __bfloat162float(h[j]));
    }
    const int e = i * 8;
    const int r = e >> 11, k = e & 2047;
    const int rr = r & 127, ch = (k & 31) >> 3;
    const size_t off = ((size_t)((r >> 7) * 64 + (k >> 5)) << 13)
                     + (rr << 6) + (((ch + (rr >> 1)) & 3) << 4);
    *(uint4*)((char*)a.hi[m] + off) = *(uint4*)h;
    *(uint4*)((char*)a.lo[m] + off) = *(uint4*)l;
}

// ------------- fused fp32 -> blocked swizzled fp16 (wo) ---------------------
__global__ __launch_bounds__(256)
void split_half(const float* __restrict__ src, __half* __restrict__ dst, int n) {
    const int i = blockIdx.x * 256 + threadIdx.x;
    if (i >= n) return;
    const float4* p = (const float4*)src + (size_t)i * 2;
    float4 va = p[0], vb = p[1];
    float f[8] = {va.x, va.y, va.z, va.w, vb.x, vb.y, vb.z, vb.w};
    __half h[8];
#pragma unroll
    for (int j = 0; j < 8; j++) h[j] = __float2half_rn(f[j]);
    const int e = i * 8;
    const int r = e >> 11, k = e & 2047;
    const int rr = r & 127, ch = (k & 31) >> 3;
    const size_t off = ((size_t)((r >> 7) * 64 + (k >> 5)) << 13)
                     + (rr << 6) + (((ch + (rr >> 1)) & 3) << 4);
    *(uint4*)((char*)dst + off) = *(uint4*)h;
}

// ---------------------------------------------------------------------------
// bf16x3 GEMM mainloop: 256x128 tile, 8 warps (4x2), warp 64x64. (R6/R11 core)
// 4-stage bulk pipeline, stage = 48KB.
// ---------------------------------------------------------------------------
#define GSTG 49152u
__device__ __forceinline__ void gemm_core256(
        uint32_t sb, int tid, int lane, int wm, int wn,
        const char* Ath, const char* Atl, const char* Bth, const char* Btl,
        float acc[4][8][4]) {
    const uint32_t fb = sb + 4 * GSTG;
    if (tid == 0) {
        mbar_init(fb, 1); mbar_init(fb + 8, 1);
        mbar_init(fb + 16, 1); mbar_init(fb + 24, 1);
        asm volatile("fence.mbarrier_init.release.cluster;" ::: "memory");
    }
    __syncthreads();
    auto gissue = [&](int s_) {
        uint32_t mb  = fb + ((s_ & 3) << 3);
        uint32_t dst = sb + (uint32_t)(s_ & 3) * GSTG;
        size_t   off = (size_t)s_ * 8192;
        mbar_expect(mb, GSTG);
        bulk_ld(dst,           Ath + off,          8192, mb);
        bulk_ld(dst + 8192u,   Ath + 524288 + off, 8192, mb);
        bulk_ld(dst + 16384u,  Atl + off,          8192, mb);
        bulk_ld(dst + 24576u,  Atl + 524288 + off, 8192, mb);
        bulk_ld(dst + 32768u,  Bth + off,          8192, mb);
        bulk_ld(dst + 40960u,  Btl + off,          8192, mb);
    };
    if (tid == 0) { gissue(0); gissue(1); gissue(2); }

    const int ra = wm * 64 + (lane & 7) + ((lane >> 3) & 1) * 8;
    const int ca = (lane >> 4) & 1;
    const int rb2 = wn * 64 + (lane & 7) + ((lane >> 4) & 1) * 8;
    const int cb = (lane >> 3) & 1;

    for (int s = 0; s < 64; s++) {
        wait_parity(fb + ((s & 3) << 3), (s >> 2) & 1);
        const uint32_t bufA = sb + (uint32_t)(s & 3) * GSTG;
        const uint32_t bufB = bufA + 32768u;
#pragma unroll
        for (int ks = 0; ks < 2; ks++) {
            uint32_t ah[4][4], al[4][4], bh[8][2], bl[8][2];
#pragma unroll
            for (int mi = 0; mi < 4; mi++) {
                int r = ra + mi * 16;
                int c = ks * 2 + ca;
                uint32_t ad = bufA + r * 64 + (((c + (r >> 1)) & 3) << 4);
                LDM4(ah[mi][0], ah[mi][1], ah[mi][2], ah[mi][3], ad);
                LDM4(al[mi][0], al[mi][1], al[mi][2], al[mi][3], ad + 16384u);
            }
#pragma unroll
            for (int np = 0; np < 4; np++) {
                int r = rb2 + np * 16;
                int c = ks * 2 + cb;
                uint32_t bd = bufB + r * 64 + (((c + (r >> 1)) & 3) << 4);
                LDM4(bh[2*np][0], bh[2*np][1], bh[2*np+1][0], bh[2*np+1][1], bd);
                LDM4(bl[2*np][0], bl[2*np][1], bl[2*np+1][0], bl[2*np+1][1], bd + 8192u);
            }
#pragma unroll
            for (int mi = 0; mi < 4; mi++)
#pragma unroll
                for (int ni = 0; ni < 8; ni++) {
                    MMA(acc[mi][ni], ah[mi], bh[ni]);
                    MMA(acc[mi][ni], ah[mi], bl[ni]);
                    MMA(acc[mi][ni], al[mi], bh[ni]);
                }
        }
        __syncthreads();
        if (tid == 0 && s + 3 < 64) gissue(s + 3);
    }
}

// ---------------------------------------------------------------------------
// fp16 GEMM mainloop: 256x128 tile, 1 MMA/MAC, 5-stage ring (24KB). (R12 core)
// ---------------------------------------------------------------------------
#define HSTG 24576u
#define HNST 5
__device__ __forceinline__ void gemm_core256_f16(
        uint32_t sb, int tid, int lane, int wm, int wn,
        const char* Ath, const char* Bth, float acc[4][8][4]) {
    const uint32_t fb = sb + HNST * HSTG;
    if (tid == 0) {
#pragma unroll
        for (int i = 0; i < HNST; i++) mbar_init(fb + i * 8, 1);
        asm volatile("fence.mbarrier_init.release.cluster;" ::: "memory");
    }
    __syncthreads();
    auto gissue = [&](int s_) {
        int slot = s_ % HNST;
        uint32_t mb  = fb + (slot << 3);
        uint32_t dst = sb + (uint32_t)slot * HSTG;
        size_t   off = (size_t)s_ * 8192;
        mbar_expect(mb, HSTG);
        bulk_ld(dst,           Ath + off,          8192, mb);
        bulk_ld(dst + 8192u,   Ath + 524288 + off, 8192, mb);
        bulk_ld(dst + 16384u,  Bth + off,          8192, mb);
    };
    if (tid == 0) { gissue(0); gissue(1); gissue(2); gissue(3); }

    const int ra = wm * 64 + (lane & 7) + ((lane >> 3) & 1) * 8;
    const int ca = (lane >> 4) & 1;
    const int rb2 = wn * 64 + (lane & 7) + ((lane >> 4) & 1) * 8;
    const int cb = (lane >> 3) & 1;

    for (int s = 0; s < 64; s++) {
        int slot = s % HNST;
        wait_parity(fb + (slot << 3), (uint32_t)((s / HNST) & 1));
        const uint32_t bufA = sb + (uint32_t)slot * HSTG;
        const uint32_t bufB = bufA + 16384u;
#pragma unroll
        for (int ks = 0; ks < 2; ks++) {
            uint32_t ah[4][4], bh[8][2];
#pragma unroll
            for (int mi = 0; mi < 4; mi++) {
                int r = ra + mi * 16;
                int c = ks * 2 + ca;
                uint32_t ad = bufA + r * 64 + (((c + (r >> 1)) & 3) << 4);
                LDM4(ah[mi][0], ah[mi][1], ah[mi][2], ah[mi][3], ad);
            }
#pragma unroll
            for (int np = 0; np < 4; np++) {
                int r = rb2 + np * 16;
                int c = ks * 2 + cb;
                uint32_t bd = bufB + r * 64 + (((c + (r >> 1)) & 3) << 4);
                LDM4(bh[2*np][0], bh[2*np][1], bh[2*np+1][0], bh[2*np+1][1], bd);
            }
#pragma unroll
            for (int mi = 0; mi < 4; mi++)
#pragma unroll
                for (int ni = 0; ni < 8; ni++)
                    MMAH(acc[mi][ni], ah[mi], bh[ni][0], bh[ni][1]);
        }
        __syncthreads();
        if (tid == 0 && s + 4 < 64) gissue(s + 4);
    }
}

// ---------------------------------------------------------------------------
// Fused Q/K/V projection GEMM (bf16x3), epilogue -> attention tiles. (R11)
// ---------------------------------------------------------------------------
__global__ __launch_bounds__(256, 1)
void gemm_qkv(const __nv_bfloat16* __restrict__ xh, const __nv_bfloat16* __restrict__ xl,
              const __nv_bfloat16* __restrict__ wqh, const __nv_bfloat16* __restrict__ wql,
              const __nv_bfloat16* __restrict__ wkh, const __nv_bfloat16* __restrict__ wkl,
              const __nv_bfloat16* __restrict__ wvh, const __nv_bfloat16* __restrict__ wvl,
              __nv_bfloat16* __restrict__ qh, __nv_bfloat16* __restrict__ ql,
              __nv_bfloat16* __restrict__ kh, __nv_bfloat16* __restrict__ kl,
              __nv_bfloat16* __restrict__ vh, __nv_bfloat16* __restrict__ vl) {
    extern __shared__ __align__(1024) char smem[];
    const uint32_t sb = s2u(smem);
    const int tid = threadIdx.x, lane = tid & 31, wid = tid >> 5;
    const int wm = wid >> 1, wn = wid & 1;
    const int bx = blockIdx.x, br = blockIdx.y * 256;

    int sel, bc;
    const __nv_bfloat16 *Bh, *Bl;
    __nv_bfloat16 *Dh, *Dl;
    if (bx < 16)      { sel = 0; bc = bx * 128;        Bh = wqh; Bl = wql; Dh = qh; Dl = ql; }
    else if (bx < 20) { sel = 1; bc = (bx - 16) * 128; Bh = wkh; Bl = wkl; Dh = kh; Dl = kl; }
    else              { sel = 2; bc = (bx - 20) * 128; Bh = wvh; Bl = wvl; Dh = vh; Dl = vl; }

    float acc[4][8][4];
#pragma unroll
    for (int mi = 0; mi < 4; mi++)
#pragma unroll
        for (int ni = 0; ni < 8; ni++)
#pragma unroll
            for (int r = 0; r < 4; r++) acc[mi][ni][r] = 0.f;

    gemm_core256(sb, tid, lane, wm, wn,
                 (const char*)xh + (size_t)(br >> 7) * 524288,
                 (const char*)xl + (size_t)(br >> 7) * 524288,
                 (const char*)Bh + (size_t)(bc >> 7) * 524288,
                 (const char*)Bl + (size_t)(bc >> 7) * 524288, acc);

    const int g = lane >> 2, t4 = lane & 3;
    const int nheads16 = (sel == 0) ? 32 * 16 : 8 * 16;
#pragma unroll
    for (int mi = 0; mi < 4; mi++) {
        int row = br + wm * 64 + mi * 16 + g;
        int b = row >> 11, t = row & 2047;
        int rb2 = t >> 7, rr = t & 127;
#pragma unroll
        for (int ni = 0; ni < 8; ni++) {
            int col = bc + wn * 64 + ni * 8 + t4 * 2;
            int hh = col >> 6, c = col & 63;
            size_t tile = (size_t)b * nheads16 + (size_t)hh * 16 + rb2;
            uint32_t h01 = packbf(acc[mi][ni][1], acc[mi][ni][0]);
            uint32_t l01 = packbf(acc[mi][ni][1] - bfhi(h01), acc[mi][ni][0] - bflo(h01));
            uint32_t h23 = packbf(acc[mi][ni][3], acc[mi][ni][2]);
            uint32_t l23 = packbf(acc[mi][ni][3] - bfhi(h23), acc[mi][ni][2] - bflo(h23));
            size_t o0 = (tile << 14) + rr * 128
                      + ((((c >> 3) + (rr & 7)) & 7) << 4) + (c & 7) * 2;
            int rr8 = rr + 8;
            size_t o1 = (tile << 14) + rr8 * 128
                      + ((((c >> 3) + (rr8 & 7)) & 7) << 4) + (c & 7) * 2;
            *(uint32_t*)((char*)Dh + o0) = h01;
            *(uint32_t*)((char*)Dl + o0) = l01;
            *(uint32_t*)((char*)Dh + o1) = h23;
            *(uint32_t*)((char*)Dl + o1) = l23;
        }
    }
}

// ---------------------------------------------------------------------------
// Output projection GEMM (fp16, R12 core): out fp32 row-major.
// ---------------------------------------------------------------------------
__global__ __launch_bounds__(256, 1)
void gemm_o(const __half* __restrict__ oh, const __half* __restrict__ woh,
            float* __restrict__ out) {
    extern __shared__ __align__(1024) char smem[];
    const uint32_t sb = s2u(smem);
    const int tid = threadIdx.x, lane = tid & 31, wid = tid >> 5;
    const int wm = wid >> 1, wn = wid & 1;
    const int br = blockIdx.y * 256, bc = blockIdx.x * 128;

    float acc[4][8][4];
#pragma unroll
    for (int mi = 0; mi < 4; mi++)
#pragma unroll
        for (int ni = 0; ni < 8; ni++)
#pragma unroll
            for (int r = 0; r < 4; r++) acc[mi][ni][r] = 0.f;

    gemm_core256_f16(sb, tid, lane, wm, wn,
                     (const char*)oh + (size_t)(br >> 7) * 524288,
                     (const char*)woh + (size_t)(bc >> 7) * 524288, acc);

    const int g = lane >> 2, t4 = lane & 3;
#pragma unroll
    for (int mi = 0; mi < 4; mi++)
#pragma unroll
        for (int ni = 0; ni < 8; ni++) {
            int row = br + wm * 64 + mi * 16 + g;
            int col = bc + wn * 64 + ni * 8 + t4 * 2;
            *(float2*)(out + (size_t)row * C_ + col) =
                make_float2(acc[mi][ni][0], acc[mi][ni][1]);
            *(float2*)(out + (size_t)(row + 8) * C_ + col) =
                make_float2(acc[mi][ni][2], acc[mi][ni][3]);
        }
}

// ---------------------------------------------------------------------------
// Flash attention (mma.sync bf16x3), 3-stage bulk KV ring, warp-drift + LPT.
// Output: fp16 (gemm_o's A operand), GEMM-A blocked layout.
// ---------------------------------------------------------------------------
__global__ __launch_bounds__(256, 1)
void attn_mma(const __nv_bfloat16* __restrict__ Qh, const __nv_bfloat16* __restrict__ Ql,
              const __nv_bfloat16* __restrict__ Kh, const __nv_bfloat16* __restrict__ Kl,
              const __nv_bfloat16* __restrict__ Vh, const __nv_bfloat16* __restrict__ Vl,
              __half* __restrict__ Oh) {
    extern __shared__ __align__(1024) char smem[];
    const uint32_t sb = s2u(smem);
    const uint32_t fb = sb + 229376u;
    const int tid = threadIdx.x, lane = tid & 31, wid = tid >> 5;
    const int qb = 15 - blockIdx.x;
    const int bh = blockIdx.y;
    const int b = bh >> 5, h = bh & 31, kvh = h >> 2;
    const int g = lane >> 2, t4 = lane & 3;
    const float F = 0.125f * 1.44269504089f;

    if (tid == 0) {
        mbar_init(fb, 1);
        mbar_init(fb + 8, 1);  mbar_init(fb + 16, 1); mbar_init(fb + 24, 1);
        mbar_init(fb + 32, 8); mbar_init(fb + 40, 8); mbar_init(fb + 48, 8);
        asm volatile("fence.mbarrier_init.release.cluster;" ::: "memory");
    }
    __syncthreads();

    const size_t qtb = ((size_t)(b * 32 + h) * 16 + qb) << 14;
    auto issueKV = [&](int kb) {
        int slot = kb % 3;
        uint32_t mb  = fb + 8 + (slot << 3);
        uint32_t dst = sb + 32768u + (uint32_t)slot * 65536u;
        size_t toff  = ((size_t)(b * 8 + kvh) * 16 + kb) << 14;
        mbar_expect(mb, 65536u);
        bulk_ld(dst,           (const char*)Kh + toff, 16384, mb);
        bulk_ld(dst + 16384u,  (const char*)Kl + toff, 16384, mb);
        bulk_ld(dst + 32768u,  (const char*)Vh + toff, 16384, mb);
        bulk_ld(dst + 49152u,  (const char*)Vl + toff, 16384, mb);
    };
    if (tid == 0) {
        mbar_expect(fb, 32768u);
        bulk_ld(sb,           (const char*)Qh + qtb, 16384, fb);
        bulk_ld(sb + 16384u,  (const char*)Ql + qtb, 16384, fb);
        issueKV(0);
        if (qb >= 1) issueKV(1);
    }

    wait_parity(fb, 0);
    uint32_t qfh[4][4], qfl[4][4];
    {
        int r = 16 * wid + (lane & 7) + ((lane >> 3) & 1) * 8;
#pragma unroll
        for (int ki = 0; ki < 4; ki++) {
            int c8 = ki * 2 + ((lane >> 4) & 1);
            uint32_t ad = sb + r * 128 + (((c8 + (r & 7)) & 7) << 4);
            LDM4(qfh[ki][0], qfh[ki][1], qfh[ki][2], qfh[ki][3], ad);
            LDM4(qfl[ki][0], qfl[ki][1], qfl[ki][2], qfl[ki][3], ad + 16384u);
        }
    }

    float oacc[8][4];
#pragma unroll
    for (int i = 0; i < 8; i++)
#pragma unroll
        for (int j = 0; j < 4; j++) oacc[i][j] = 0.f;
    float m0 = -1e30f, m1 = -1e30f, l0 = 0.f, l1 = 0.f;

    for (int kb = 0; kb <= qb; kb++) {
        if (tid == 0) {
            int n = kb + 2;
            if (n <= qb) {
                if (n >= 3)
                    wait_parity(fb + 32 + ((n % 3) << 3), (uint32_t)(((n - 3) / 3) & 1));
                issueKV(n);
            }
        }
        wait_parity(fb + 8 + ((kb % 3) << 3), (uint32_t)((kb / 3) & 1));
        const uint32_t base = sb + 32768u + (uint32_t)(kb % 3) * 65536u;

        // ---- S = Q K^T (bf16x3)
        float s[16][4];
#pragma unroll
        for (int i = 0; i < 16; i++)
#pragma unroll
            for (int j = 0; j < 4; j++) s[i][j] = 0.f;
        {
            int rk = (lane & 7) + ((lane >> 3) & 1) * 8;
#pragma unroll
            for (int n2 = 0; n2 < 8; n2++) {
                int row = n2 * 16 + rk;
#pragma unroll
                for (int ki = 0; ki < 4; ki++) {
                    int c8 = ki * 2 + ((lane >> 4) & 1);
                    uint32_t ad = base + row * 128 + (((c8 + (row & 7)) & 7) << 4);
                    uint32_t k0, k1, k2, k3, e0, e1, e2, e3;
                    LDM4(k0, k1, k2, k3, ad);
                    LDM4(e0, e1, e2, e3, ad + 16384u);
                    MMAB(s[2*n2],   qfh[ki], k0, k2);
                    MMAB(s[2*n2],   qfh[ki], e0, e2);
                    MMAB(s[2*n2],   qfl[ki], k0, k2);
                    MMAB(s[2*n2+1], qfh[ki], k1, k3);
                    MMAB(s[2*n2+1], qfh[ki], e1, e3);
                    MMAB(s[2*n2+1], qfl[ki], k1, k3);
                }
            }
        }
        if (kb == qb) {
            int rl = 16 * wid + g;
#pragma unroll
            for (int ni = 0; ni < 16; ni++) {
                int c = ni * 8 + t4 * 2;
                if (c     > rl)     s[ni][0] = -1e30f;
                if (c + 1 > rl)     s[ni][1] = -1e30f;
                if (c     > rl + 8) s[ni][2] = -1e30f;
                if (c + 1 > rl + 8) s[ni][3] = -1e30f;
            }
        }
        // ---- online softmax
        float mx0 = -1e30f, mx1 = -1e30f;
#pragma unroll
        for (int ni = 0; ni < 16; ni++) {
            mx0 = fmaxf(mx0, fmaxf(s[ni][0], s[ni][1]));
            mx1 = fmaxf(mx1, fmaxf(s[ni][2], s[ni][3]));
        }
        mx0 = fmaxf(mx0, __shfl_xor_sync(0xffffffffu, mx0, 1));
        mx0 = fmaxf(mx0, __shfl_xor_sync(0xffffffffu, mx0, 2));
        mx1 = fmaxf(mx1, __shfl_xor_sync(0xffffffffu, mx1, 1));
        mx1 = fmaxf(mx1, __shfl_xor_sync(0xffffffffu, mx1, 2));
        float mn0 = fmaxf(m0, mx0 * F), mn1 = fmaxf(m1, mx1 * F);
        float a0 = ex2f(m0 - mn0), a1 = ex2f(m1 - mn1);
        l0 *= a0; l1 *= a1;
#pragma unroll
        for (int ni = 0; ni < 8; ni++) {
            oacc[ni][0] *= a0; oacc[ni][1] *= a0;
            oacc[ni][2] *= a1; oacc[ni][3] *= a1;
        }
        m0 = mn0; m1 = mn1;

        uint32_t pa[16], pb[16], la[16], lb[16];
#pragma unroll
        for (int ni = 0; ni < 16; ni++) {
            float p0 = ex2f(fmaf(s[ni][0], F, -mn0));
            float p1 = ex2f(fmaf(s[ni][1], F, -mn0));
            float p2 = ex2f(fmaf(s[ni][2], F, -mn1));
            float p3 = ex2f(fmaf(s[ni][3], F, -mn1));
            l0 += p0 + p1; l1 += p2 + p3;
            uint32_t hA = packbf(p1, p0), hB = packbf(p3, p2);
            pa[ni] = hA; pb[ni] = hB;
            la[ni] = packbf(p1 - bfhi(hA), p0 - bflo(hA));
            lb[ni] = packbf(p3 - bfhi(hB), p2 - bflo(hB));
        }

        // ---- O += P V (bf16x3)
        {
            const uint32_t baseV = base + 32768u;
            int rv = (lane & 7) + ((lane >> 3) & 1) * 8;
#pragma unroll
            for (int ki = 0; ki < 8; ki++) {
                uint32_t ah[4] = {pa[2*ki], pb[2*ki], pa[2*ki+1], pb[2*ki+1]};
                uint32_t al[4] = {la[2*ki], lb[2*ki], la[2*ki+1], lb[2*ki+1]};
                int row = ki * 16 + rv;
#pragma unroll
                for (int dv = 0; dv < 4; dv++) {
                    int c8 = dv * 2 + ((lane >> 4) & 1);
                    uint32_t ad = baseV + row * 128 + (((c8 + (row & 7)) & 7) << 4);
                    uint32_t v0, v1, v2, v3, w0, w1, w2, w3;
                    LDM4T(v0, v1, v2, v3, ad);
                    LDM4T(w0, w1, w2, w3, ad + 16384u);
                    MMAB(oacc[2*dv],   ah, v0, v1);
                    MMAB(oacc[2*dv],   ah, w0, w1);
                    MMAB(oacc[2*dv],   al, v0, v1);
                    MMAB(oacc[2*dv+1], ah, v2, v3);
                    MMAB(oacc[2*dv+1], ah, w2, w3);
                    MMAB(oacc[2*dv+1], al, v2, v3);
                }
            }
        }
        if (lane == 0) mbar_arrive(fb + 32 + ((kb % 3) << 3));
    }

    // ---- epilogue: write O as fp16 in GEMM-A blocked layout
    l0 += __shfl_xor_sync(0xffffffffu, l0, 1);
    l0 += __shfl_xor_sync(0xffffffffu, l0, 2);
    l1 += __shfl_xor_sync(0xffffffffu, l1, 1);
    l1 += __shfl_xor_sync(0xffffffffu, l1, 2);
    const float i0 = 1.f / l0, i1 = 1.f / l1;
    const int rr0 = 16 * wid + g;
    const int rowg = b * 2048 + qb * 128 + rr0;
    const int rowBlk = rowg >> 7;
#pragma unroll
    for (int ni = 0; ni < 8; ni++) {
        int cg = h * 64 + ni * 8 + t4 * 2;
        int tile = rowBlk * 64 + (cg >> 5);
        int cc = cg & 31, ch = cc >> 3;
        __half2 h2a = __floats2half2_rn(oacc[ni][0] * i0, oacc[ni][1] * i0);
        __half2 h2b = __floats2half2_rn(oacc[ni][2] * i1, oacc[ni][3] * i1);
        int rr1 = rr0 + 8;
        size_t o0 = ((size_t)tile << 13) + rr0 * 64 + (((ch + (rr0 >> 1)) & 3) << 4) + (cc & 7) * 2;
        size_t o1 = ((size_t)tile << 13) + rr1 * 64 + (((ch + (rr1 >> 1)) & 3) << 4) + (cc & 7) * 2;
        *(__half2*)((char*)Oh + o0) = h2a;
        *(__half2*)((char*)Oh + o1) = h2b;
    }
}

// ---------------------------------------------------------------------------
extern "C" void kernel_launch(void* const* d_in, const int* in_sizes, int n_in,
                              void* d_out, int out_size) {
    const float* x  = (const float*)d_in[0];
    const float* wq = (const float*)d_in[1];
    const float* wk = (const float*)d_in[2];
    const float* wv = (const float*)d_in[3];
    const float* wo = (const float*)d_in[4];
    float* out = (float*)d_out;

    __nv_bfloat16 *xh, *xl, *wqh, *wql, *wkh, *wkl, *wvh, *wvl;
    __nv_bfloat16 *qh, *ql, *kh, *kl, *vh, *vl;
    __half *woh, *oh;
    cudaGetSymbolAddress((void**)&xh, g_xh);   cudaGetSymbolAddress((void**)&xl, g_xl);
    cudaGetSymbolAddress((void**)&wqh, g_wqh); cudaGetSymbolAddress((void**)&wql, g_wql);
    cudaGetSymbolAddress((void**)&wkh, g_wkh); cudaGetSymbolAddress((void**)&wkl, g_wkl);
    cudaGetSymbolAddress((void**)&wvh, g_wvh); cudaGetSymbolAddress((void**)&wvl, g_wvl);
    cudaGetSymbolAddress((void**)&qh, g_qh);   cudaGetSymbolAddress((void**)&ql, g_ql);
    cudaGetSymbolAddress((void**)&kh, g_kh);   cudaGetSymbolAddress((void**)&kl, g_kl);
    cudaGetSymbolAddress((void**)&vh, g_vh);   cudaGetSymbolAddress((void**)&vl, g_vl);
    cudaGetSymbolAddress((void**)&woh, g_woh);
    cudaGetSymbolAddress((void**)&oh, g_oh);

    const int GSB = 4 * 49152 + 32;     // bf16x3 core smem
    const int GSH = HNST * 24576 + 40;  // fp16 core smem
    const int AS  = 229376 + 56;
    cudaFuncSetAttribute(gemm_qkv, cudaFuncAttributeMaxDynamicSharedMemorySize, GSB);
    cudaFuncSetAttribute(gemm_o,   cudaFuncAttributeMaxDynamicSharedMemorySize, GSH);
    cudaFuncSetAttribute(attn_mma, cudaFuncAttributeMaxDynamicSharedMemorySize, AS);

    SplitArgs sa;
    sa.src[0] = x;  sa.hi[0] = xh;  sa.lo[0] = xl;  sa.nchunk[0] = M_ * C_ / 8;
    sa.src[1] = wq; sa.hi[1] = wqh; sa.lo[1] = wql; sa.nchunk[1] = C_ * C_ / 8;
    sa.src[2] = wk; sa.hi[2] = wkh; sa.lo[2] = wkl; sa.nchunk[2] = KVC * C_ / 8;
    sa.src[3] = wv; sa.hi[3] = wvh; sa.lo[3] = wvl; sa.nchunk[3] = KVC * C_ / 8;
    split_all<<<dim3((M_ * C_ / 8 + 255) / 256, 4), 256>>>(sa);
    split_half<<<(C_ * C_ / 8 + 255) / 256, 256>>>(wo, woh, C_ * C_ / 8);

    gemm_qkv<<<dim3(24, 16), 256, GSB>>>(xh, xl, wqh, wql, wkh, wkl, wvh, wvl,
                                         qh, ql, kh, kl, vh, vl);
    attn_mma<<<dim3(T_ / 128, B_ * HQ), 256, AS>>>(qh, ql, kh, kl, vh, vl, oh);
    gemm_o<<<dim3(16, 16), 256, GSH>>>(oh, woh, out);
}

// round 15
// speedup vs baseline: 1.3177x; 1.1312x over previous
#include <cuda_runtime.h>
#include <cuda_bf16.h>
#include <cuda_fp16.h>
#include <cstdint>
#include <cstddef>

#define B_  2
#define T_  2048
#define C_  2048
#define HQ  32
#define HKV 8
#define HD  64
#define M_  (B_*T_)      // 4096
#define KVC (HKV*HD)     // 512

// ------------------------- scratch (no cudaMalloc) -------------------------
// bf16 hi/lo (projection inputs + V attention operand)
__device__ __nv_bfloat16 g_xh[(size_t)M_*C_],  g_xl[(size_t)M_*C_];
__device__ __nv_bfloat16 g_wqh[(size_t)C_*C_], g_wql[(size_t)C_*C_];
__device__ __nv_bfloat16 g_wkh[(size_t)KVC*C_],g_wkl[(size_t)KVC*C_];
__device__ __nv_bfloat16 g_wvh[(size_t)KVC*C_],g_wvl[(size_t)KVC*C_];
__device__ __nv_bfloat16 g_vh[(size_t)M_*KVC], g_vl[(size_t)M_*KVC];
// fp16 single (Q, K attention operands + output-projection operands)
__device__ __half g_qh[(size_t)M_*C_];
__device__ __half g_kh[(size_t)M_*KVC];
__device__ __half g_woh[(size_t)C_*C_];
__device__ __half g_oh[(size_t)M_*C_];

// ------------------------- helpers -----------------------------------------
__device__ __forceinline__ uint32_t s2u(const void* p) {
    uint32_t a;
    asm("{ .reg .u64 t; cvta.to.shared.u64 t, %1; cvt.u32.u64 %0, t; }"
        : "=r"(a) : "l"(p));
    return a;
}
__device__ __forceinline__ void bulk_ld(uint32_t dst, const void* src,
                                        uint32_t bytes, uint32_t mbar) {
    asm volatile(
        "cp.async.bulk.shared::cluster.global.mbarrier::complete_tx::bytes "
        "[%0], [%1], %2, [%3];"
        :: "r"(dst), "l"(src), "r"(bytes), "r"(mbar) : "memory");
}
__device__ __forceinline__ void mbar_init(uint32_t mbar, uint32_t cnt) {
    asm volatile("mbarrier.init.shared.b64 [%0], %1;" :: "r"(mbar), "r"(cnt) : "memory");
}
__device__ __forceinline__ void mbar_expect(uint32_t mbar, uint32_t tx) {
    asm volatile("mbarrier.arrive.expect_tx.shared.b64 _, [%0], %1;"
                 :: "r"(mbar), "r"(tx) : "memory");
}
__device__ __forceinline__ void mbar_arrive(uint32_t mbar) {
    asm volatile("mbarrier.arrive.shared.b64 _, [%0];" :: "r"(mbar) : "memory");
}
__device__ __forceinline__ void wait_parity(uint32_t mbar, uint32_t phase) {
    asm volatile(
        "{ .reg .pred P1;\n"
        "WL%=:\n"
        " mbarrier.try_wait.parity.acquire.cta.shared::cta.b64 P1, [%0], %1, 0x989680;\n"
        " @P1 bra.uni WD%=;\n"
        " bra.uni WL%=;\n"
        "WD%=:\n }"
        :: "r"(mbar), "r"(phase) : "memory");
}
#define LDM4(r0,r1,r2,r3,addr) \
    asm volatile("ldmatrix.sync.aligned.m8n8.x4.shared.b16 {%0,%1,%2,%3}, [%4];" \
                 : "=r"(r0),"=r"(r1),"=r"(r2),"=r"(r3) : "r"(addr))
#define LDM4T(r0,r1,r2,r3,addr) \
    asm volatile("ldmatrix.sync.aligned.m8n8.x4.trans.shared.b16 {%0,%1,%2,%3}, [%4];" \
                 : "=r"(r0),"=r"(r1),"=r"(r2),"=r"(r3) : "r"(addr))
#define MMA(d,a,b) \
    asm volatile("mma.sync.aligned.m16n8k16.row.col.f32.bf16.bf16.f32 " \
                 "{%0,%1,%2,%3},{%4,%5,%6,%7},{%8,%9},{%0,%1,%2,%3};" \
                 : "+f"((d)[0]),"+f"((d)[1]),"+f"((d)[2]),"+f"((d)[3]) \
                 : "r"((a)[0]),"r"((a)[1]),"r"((a)[2]),"r"((a)[3]), \
                   "r"((b)[0]),"r"((b)[1]))
#define MMAB(d,a,b0,b1) \
    asm volatile("mma.sync.aligned.m16n8k16.row.col.f32.bf16.bf16.f32 " \
                 "{%0,%1,%2,%3},{%4,%5,%6,%7},{%8,%9},{%0,%1,%2,%3};" \
                 : "+f"((d)[0]),"+f"((d)[1]),"+f"((d)[2]),"+f"((d)[3]) \
                 : "r"((a)[0]),"r"((a)[1]),"r"((a)[2]),"r"((a)[3]), \
                   "r"(b0),"r"(b1))
#define MMAH(d,a,b0,b1) \
    asm volatile("mma.sync.aligned.m16n8k16.row.col.f32.f16.f16.f32 " \
                 "{%0,%1,%2,%3},{%4,%5,%6,%7},{%8,%9},{%0,%1,%2,%3};" \
                 : "+f"((d)[0]),"+f"((d)[1]),"+f"((d)[2]),"+f"((d)[3]) \
                 : "r"((a)[0]),"r"((a)[1]),"r"((a)[2]),"r"((a)[3]), \
                   "r"(b0),"r"(b1))

__device__ __forceinline__ float ex2f(float x) {
    float r; asm("ex2.approx.f32 %0,%1;" : "=f"(r) : "f"(x)); return r;
}
__device__ __forceinline__ uint32_t packbf(float hi, float lo) {
    uint32_t r; asm("cvt.rn.bf16x2.f32 %0,%1,%2;" : "=r"(r) : "f"(hi), "f"(lo));
    return r;
}
__device__ __forceinline__ float bflo(uint32_t v) { return __uint_as_float(v << 16); }
__device__ __forceinline__ float bfhi(uint32_t v) { return __uint_as_float(v & 0xffff0000u); }

// ------------- fused fp32 -> blocked swizzled bf16 hi/lo (x, wq, wk, wv) ----
struct SplitArgs {
    const float* src[4];
    __nv_bfloat16* hi[4];
    __nv_bfloat16* lo[4];
    int nchunk[4];
};
__global__ __launch_bounds__(256)
void split_all(SplitArgs a) {
    const int m = blockIdx.y;
    const int i = blockIdx.x * 256 + threadIdx.x;
    if (i >= a.nchunk[m]) return;
    const float4* p = (const float4*)a.src[m] + (size_t)i * 2;
    float4 va = p[0], vb = p[1];
    float f[8] = {va.x, va.y, va.z, va.w, vb.x, vb.y, vb.z, vb.w};
    __nv_bfloat16 h[8], l[8];
#pragma unroll
    for (int j = 0; j < 8; j++) {
        h[j] = __float2bfloat16(f[j]);
        l[j] = __float2bfloat16(f[j] - __bfloat162float(h[j]));
    }
    const int e = i * 8;
    const int r = e >> 11, k = e & 2047;
    const int rr = r & 127, ch = (k & 31) >> 3;
    const size_t off = ((size_t)((r >> 7) * 64 + (k >> 5)) << 13)
                     + (rr << 6) + (((ch + (rr >> 1)) & 3) << 4);
    *(uint4*)((char*)a.hi[m] + off) = *(uint4*)h;
    *(uint4*)((char*)a.lo[m] + off) = *(uint4*)l;
}

// ------------- fused fp32 -> blocked swizzled fp16 (wo) ---------------------
__global__ __launch_bounds__(256)
void split_half(const float* __restrict__ src, __half* __restrict__ dst, int n) {
    const int i = blockIdx.x * 256 + threadIdx.x;
    if (i >= n) return;
    const float4* p = (const float4*)src + (size_t)i * 2;
    float4 va = p[0], vb = p[1];
    float f[8] = {va.x, va.y, va.z, va.w, vb.x, vb.y, vb.z, vb.w};
    __half h[8];
#pragma unroll
    for (int j = 0; j < 8; j++) h[j] = __float2half_rn(f[j]);
    const int e = i * 8;
    const int r = e >> 11, k = e & 2047;
    const int rr = r & 127, ch = (k & 31) >> 3;
    const size_t off = ((size_t)((r >> 7) * 64 + (k >> 5)) << 13)
                     + (rr << 6) + (((ch + (rr >> 1)) & 3) << 4);
    *(uint4*)((char*)dst + off) = *(uint4*)h;
}

// ---------------------------------------------------------------------------
// bf16x3 GEMM mainloop: 256x128 tile, 8 warps (4x2), warp 64x64. (R6/R11 core)
// ---------------------------------------------------------------------------
#define GSTG 49152u
__device__ __forceinline__ void gemm_core256(
        uint32_t sb, int tid, int lane, int wm, int wn,
        const char* Ath, const char* Atl, const char* Bth, const char* Btl,
        float acc[4][8][4]) {
    const uint32_t fb = sb + 4 * GSTG;
    if (tid == 0) {
        mbar_init(fb, 1); mbar_init(fb + 8, 1);
        mbar_init(fb + 16, 1); mbar_init(fb + 24, 1);
        asm volatile("fence.mbarrier_init.release.cluster;" ::: "memory");
    }
    __syncthreads();
    auto gissue = [&](int s_) {
        uint32_t mb  = fb + ((s_ & 3) << 3);
        uint32_t dst = sb + (uint32_t)(s_ & 3) * GSTG;
        size_t   off = (size_t)s_ * 8192;
        mbar_expect(mb, GSTG);
        bulk_ld(dst,           Ath + off,          8192, mb);
        bulk_ld(dst + 8192u,   Ath + 524288 + off, 8192, mb);
        bulk_ld(dst + 16384u,  Atl + off,          8192, mb);
        bulk_ld(dst + 24576u,  Atl + 524288 + off, 8192, mb);
        bulk_ld(dst + 32768u,  Bth + off,          8192, mb);
        bulk_ld(dst + 40960u,  Btl + off,          8192, mb);
    };
    if (tid == 0) { gissue(0); gissue(1); gissue(2); }

    const int ra = wm * 64 + (lane & 7) + ((lane >> 3) & 1) * 8;
    const int ca = (lane >> 4) & 1;
    const int rb2 = wn * 64 + (lane & 7) + ((lane >> 4) & 1) * 8;
    const int cb = (lane >> 3) & 1;

    for (int s = 0; s < 64; s++) {
        wait_parity(fb + ((s & 3) << 3), (s >> 2) & 1);
        const uint32_t bufA = sb + (uint32_t)(s & 3) * GSTG;
        const uint32_t bufB = bufA + 32768u;
#pragma unroll
        for (int ks = 0; ks < 2; ks++) {
            uint32_t ah[4][4], al[4][4], bh[8][2], bl[8][2];
#pragma unroll
            for (int mi = 0; mi < 4; mi++) {
                int r = ra + mi * 16;
                int c = ks * 2 + ca;
                uint32_t ad = bufA + r * 64 + (((c + (r >> 1)) & 3) << 4);
                LDM4(ah[mi][0], ah[mi][1], ah[mi][2], ah[mi][3], ad);
                LDM4(al[mi][0], al[mi][1], al[mi][2], al[mi][3], ad + 16384u);
            }
#pragma unroll
            for (int np = 0; np < 4; np++) {
                int r = rb2 + np * 16;
                int c = ks * 2 + cb;
                uint32_t bd = bufB + r * 64 + (((c + (r >> 1)) & 3) << 4);
                LDM4(bh[2*np][0], bh[2*np][1], bh[2*np+1][0], bh[2*np+1][1], bd);
                LDM4(bl[2*np][0], bl[2*np][1], bl[2*np+1][0], bl[2*np+1][1], bd + 8192u);
            }
#pragma unroll
            for (int mi = 0; mi < 4; mi++)
#pragma unroll
                for (int ni = 0; ni < 8; ni++) {
                    MMA(acc[mi][ni], ah[mi], bh[ni]);
                    MMA(acc[mi][ni], ah[mi], bl[ni]);
                    MMA(acc[mi][ni], al[mi], bh[ni]);
                }
        }
        __syncthreads();
        if (tid == 0 && s + 3 < 64) gissue(s + 3);
    }
}

// ---------------------------------------------------------------------------
// fp16 GEMM mainloop: 256x128 tile, 1 MMA/MAC, 5-stage ring. (R12 gemm_o core)
// ---------------------------------------------------------------------------
#define HSTG 24576u
#define HNST 5
__device__ __forceinline__ void gemm_core256_f16(
        uint32_t sb, int tid, int lane, int wm, int wn,
        const char* Ath, const char* Bth, float acc[4][8][4]) {
    const uint32_t fb = sb + HNST * HSTG;
    if (tid == 0) {
#pragma unroll
        for (int i = 0; i < HNST; i++) mbar_init(fb + i * 8, 1);
        asm volatile("fence.mbarrier_init.release.cluster;" ::: "memory");
    }
    __syncthreads();
    auto gissue = [&](int s_) {
        int slot = s_ % HNST;
        uint32_t mb  = fb + (slot << 3);
        uint32_t dst = sb + (uint32_t)slot * HSTG;
        size_t   off = (size_t)s_ * 8192;
        mbar_expect(mb, HSTG);
        bulk_ld(dst,           Ath + off,          8192, mb);
        bulk_ld(dst + 8192u,   Ath + 524288 + off, 8192, mb);
        bulk_ld(dst + 16384u,  Bth + off,          8192, mb);
    };
    if (tid == 0) { gissue(0); gissue(1); gissue(2); gissue(3); }

    const int ra = wm * 64 + (lane & 7) + ((lane >> 3) & 1) * 8;
    const int ca = (lane >> 4) & 1;
    const int rb2 = wn * 64 + (lane & 7) + ((lane >> 4) & 1) * 8;
    const int cb = (lane >> 3) & 1;

    for (int s = 0; s < 64; s++) {
        int slot = s % HNST;
        wait_parity(fb + (slot << 3), (uint32_t)((s / HNST) & 1));
        const uint32_t bufA = sb + (uint32_t)slot * HSTG;
        const uint32_t bufB = bufA + 16384u;
#pragma unroll
        for (int ks = 0; ks < 2; ks++) {
            uint32_t ah[4][4], bh[8][2];
#pragma unroll
            for (int mi = 0; mi < 4; mi++) {
                int r = ra + mi * 16;
                int c = ks * 2 + ca;
                uint32_t ad = bufA + r * 64 + (((c + (r >> 1)) & 3) << 4);
                LDM4(ah[mi][0], ah[mi][1], ah[mi][2], ah[mi][3], ad);
            }
#pragma unroll
            for (int np = 0; np < 4; np++) {
                int r = rb2 + np * 16;
                int c = ks * 2 + cb;
                uint32_t bd = bufB + r * 64 + (((c + (r >> 1)) & 3) << 4);
                LDM4(bh[2*np][0], bh[2*np][1], bh[2*np+1][0], bh[2*np+1][1], bd);
            }
#pragma unroll
            for (int mi = 0; mi < 4; mi++)
#pragma unroll
                for (int ni = 0; ni < 8; ni++)
                    MMAH(acc[mi][ni], ah[mi], bh[ni][0], bh[ni][1]);
        }
        __syncthreads();
        if (tid == 0 && s + 4 < 64) gissue(s + 4);
    }
}

// ---------------------------------------------------------------------------
// Fused Q/K/V projection GEMM (bf16x3 core).
// Epilogue: Q,K -> fp16 single tiles; V -> bf16 hi/lo tiles.
// ---------------------------------------------------------------------------
__global__ __launch_bounds__(256, 1)
void gemm_qkv(const __nv_bfloat16* __restrict__ xh, const __nv_bfloat16* __restrict__ xl,
              const __nv_bfloat16* __restrict__ wqh, const __nv_bfloat16* __restrict__ wql,
              const __nv_bfloat16* __restrict__ wkh, const __nv_bfloat16* __restrict__ wkl,
              const __nv_bfloat16* __restrict__ wvh, const __nv_bfloat16* __restrict__ wvl,
              __half* __restrict__ qh, __half* __restrict__ kh,
              __nv_bfloat16* __restrict__ vh, __nv_bfloat16* __restrict__ vl) {
    extern __shared__ __align__(1024) char smem[];
    const uint32_t sb = s2u(smem);
    const int tid = threadIdx.x, lane = tid & 31, wid = tid >> 5;
    const int wm = wid >> 1, wn = wid & 1;
    const int bx = blockIdx.x, br = blockIdx.y * 256;

    int sel, bc;
    const __nv_bfloat16 *Bh, *Bl;
    if (bx < 16)      { sel = 0; bc = bx * 128;        Bh = wqh; Bl = wql; }
    else if (bx < 20) { sel = 1; bc = (bx - 16) * 128; Bh = wkh; Bl = wkl; }
    else              { sel = 2; bc = (bx - 20) * 128; Bh = wvh; Bl = wvl; }

    float acc[4][8][4];
#pragma unroll
    for (int mi = 0; mi < 4; mi++)
#pragma unroll
        for (int ni = 0; ni < 8; ni++)
#pragma unroll
            for (int r = 0; r < 4; r++) acc[mi][ni][r] = 0.f;

    gemm_core256(sb, tid, lane, wm, wn,
                 (const char*)xh + (size_t)(br >> 7) * 524288,
                 (const char*)xl + (size_t)(br >> 7) * 524288,
                 (const char*)Bh + (size_t)(bc >> 7) * 524288,
                 (const char*)Bl + (size_t)(bc >> 7) * 524288, acc);

    const int g = lane >> 2, t4 = lane & 3;
    const int nheads16 = (sel == 0) ? 32 * 16 : 8 * 16;
#pragma unroll
    for (int mi = 0; mi < 4; mi++) {
        int row = br + wm * 64 + mi * 16 + g;
        int b = row >> 11, t = row & 2047;
        int rb2 = t >> 7, rr = t & 127;
#pragma unroll
        for (int ni = 0; ni < 8; ni++) {
            int col = bc + wn * 64 + ni * 8 + t4 * 2;
            int hh = col >> 6, c = col & 63;
            size_t tile = (size_t)b * nheads16 + (size_t)hh * 16 + rb2;
            size_t o0 = (tile << 14) + rr * 128
                      + ((((c >> 3) + (rr & 7)) & 7) << 4) + (c & 7) * 2;
            int rr8 = rr + 8;
            size_t o1 = (tile << 14) + rr8 * 128
                      + ((((c >> 3) + (rr8 & 7)) & 7) << 4) + (c & 7) * 2;
            if (sel == 2) {
                uint32_t h01 = packbf(acc[mi][ni][1], acc[mi][ni][0]);
                uint32_t l01 = packbf(acc[mi][ni][1] - bfhi(h01), acc[mi][ni][0] - bflo(h01));
                uint32_t h23 = packbf(acc[mi][ni][3], acc[mi][ni][2]);
                uint32_t l23 = packbf(acc[mi][ni][3] - bfhi(h23), acc[mi][ni][2] - bflo(h23));
                *(uint32_t*)((char*)vh + o0) = h01;
                *(uint32_t*)((char*)vl + o0) = l01;
                *(uint32_t*)((char*)vh + o1) = h23;
                *(uint32_t*)((char*)vl + o1) = l23;
            } else {
                __half* D = (sel == 0) ? qh : kh;
                __half2 h2a = __floats2half2_rn(acc[mi][ni][0], acc[mi][ni][1]);
                __half2 h2b = __floats2half2_rn(acc[mi][ni][2], acc[mi][ni][3]);
                *(__half2*)((char*)D + o0) = h2a;
                *(__half2*)((char*)D + o1) = h2b;
            }
        }
    }
}

// ---------------------------------------------------------------------------
// Output projection GEMM (fp16 core): out fp32 row-major.
// ---------------------------------------------------------------------------
__global__ __launch_bounds__(256, 1)
void gemm_o(const __half* __restrict__ oh, const __half* __restrict__ woh,
            float* __restrict__ out) {
    extern __shared__ __align__(1024) char smem[];
    const uint32_t sb = s2u(smem);
    const int tid = threadIdx.x, lane = tid & 31, wid = tid >> 5;
    const int wm = wid >> 1, wn = wid & 1;
    const int br = blockIdx.y * 256, bc = blockIdx.x * 128;

    float acc[4][8][4];
#pragma unroll
    for (int mi = 0; mi < 4; mi++)
#pragma unroll
        for (int ni = 0; ni < 8; ni++)
#pragma unroll
            for (int r = 0; r < 4; r++) acc[mi][ni][r] = 0.f;

    gemm_core256_f16(sb, tid, lane, wm, wn,
                     (const char*)oh + (size_t)(br >> 7) * 524288,
                     (const char*)woh + (size_t)(bc >> 7) * 524288, acc);

    const int g = lane >> 2, t4 = lane & 3;
#pragma unroll
    for (int mi = 0; mi < 4; mi++)
#pragma unroll
        for (int ni = 0; ni < 8; ni++) {
            int row = br + wm * 64 + mi * 16 + g;
            int col = bc + wn * 64 + ni * 8 + t4 * 2;
            *(float2*)(out + (size_t)row * C_ + col) =
                make_float2(acc[mi][ni][0], acc[mi][ni][1]);
            *(float2*)(out + (size_t)(row + 8) * C_ + col) =
                make_float2(acc[mi][ni][2], acc[mi][ni][3]);
        }
}

// ---------------------------------------------------------------------------
// Flash attention: fp16-single QK, bf16x3 PV. 3-stage KV ring (48KB/stage),
// warp-drift sync + LPT. Output: fp16, GEMM-A blocked layout.
// smem: Q fp16 [16K] | 3 x {Kh fp16, Vh, Vl}[16K each]. barriers at +163840.
// ---------------------------------------------------------------------------
__global__ __launch_bounds__(256, 1)
void attn_mma(const __half* __restrict__ Qh, const __half* __restrict__ Kh,
              const __nv_bfloat16* __restrict__ Vh, const __nv_bfloat16* __restrict__ Vl,
              __half* __restrict__ Oh) {
    extern __shared__ __align__(1024) char smem[];
    const uint32_t sb = s2u(smem);
    const uint32_t fb = sb + 163840u;
    const int tid = threadIdx.x, lane = tid & 31, wid = tid >> 5;
    const int qb = 15 - blockIdx.x;              // LPT
    const int bh = blockIdx.y;
    const int b = bh >> 5, h = bh & 31, kvh = h >> 2;
    const int g = lane >> 2, t4 = lane & 3;
    const float F = 0.125f * 1.44269504089f;

    if (tid == 0) {
        mbar_init(fb, 1);
        mbar_init(fb + 8, 1);  mbar_init(fb + 16, 1); mbar_init(fb + 24, 1);
        mbar_init(fb + 32, 8); mbar_init(fb + 40, 8); mbar_init(fb + 48, 8);
        asm volatile("fence.mbarrier_init.release.cluster;" ::: "memory");
    }
    __syncthreads();

    const size_t qtb = ((size_t)(b * 32 + h) * 16 + qb) << 14;
    auto issueKV = [&](int kb) {
        int slot = kb % 3;
        uint32_t mb  = fb + 8 + (slot << 3);
        uint32_t dst = sb + 16384u + (uint32_t)slot * 49152u;
        size_t toff  = ((size_t)(b * 8 + kvh) * 16 + kb) << 14;
        mbar_expect(mb, 49152u);
        bulk_ld(dst,           (const char*)Kh + toff, 16384, mb);
        bulk_ld(dst + 16384u,  (const char*)Vh + toff, 16384, mb);
        bulk_ld(dst + 32768u,  (const char*)Vl + toff, 16384, mb);
    };
    if (tid == 0) {
        mbar_expect(fb, 16384u);
        bulk_ld(sb, (const char*)Qh + qtb, 16384, fb);
        issueKV(0);
        if (qb >= 1) issueKV(1);
    }

    wait_parity(fb, 0);
    uint32_t qf[4][4];
    {
        int r = 16 * wid + (lane & 7) + ((lane >> 3) & 1) * 8;
#pragma unroll
        for (int ki = 0; ki < 4; ki++) {
            int c8 = ki * 2 + ((lane >> 4) & 1);
            uint32_t ad = sb + r * 128 + (((c8 + (r & 7)) & 7) << 4);
            LDM4(qf[ki][0], qf[ki][1], qf[ki][2], qf[ki][3], ad);
        }
    }

    float oacc[8][4];
#pragma unroll
    for (int i = 0; i < 8; i++)
#pragma unroll
        for (int j = 0; j < 4; j++) oacc[i][j] = 0.f;
    float m0 = -1e30f, m1 = -1e30f, l0 = 0.f, l1 = 0.f;

    for (int kb = 0; kb <= qb; kb++) {
        if (tid == 0) {
            int n = kb + 2;
            if (n <= qb) {
                if (n >= 3)
                    wait_parity(fb + 32 + ((n % 3) << 3), (uint32_t)(((n - 3) / 3) & 1));
                issueKV(n);
            }
        }
        wait_parity(fb + 8 + ((kb % 3) << 3), (uint32_t)((kb / 3) & 1));
        const uint32_t base = sb + 16384u + (uint32_t)(kb % 3) * 49152u;

        // ---- S = Q K^T (fp16 single)
        float s[16][4];
#pragma unroll
        for (int i = 0; i < 16; i++)
#pragma unroll
            for (int j = 0; j < 4; j++) s[i][j] = 0.f;
        {
            int rk = (lane & 7) + ((lane >> 3) & 1) * 8;
#pragma unroll
            for (int n2 = 0; n2 < 8; n2++) {
                int row = n2 * 16 + rk;
#pragma unroll
                for (int ki = 0; ki < 4; ki++) {
                    int c8 = ki * 2 + ((lane >> 4) & 1);
                    uint32_t ad = base + row * 128 + (((c8 + (row & 7)) & 7) << 4);
                    uint32_t k0, k1, k2, k3;
                    LDM4(k0, k1, k2, k3, ad);
                    MMAH(s[2*n2],   qf[ki], k0, k2);
                    MMAH(s[2*n2+1], qf[ki], k1, k3);
                }
            }
        }
        if (kb == qb) {
            int rl = 16 * wid + g;
#pragma unroll
            for (int ni = 0; ni < 16; ni++) {
                int c = ni * 8 + t4 * 2;
                if (c     > rl)     s[ni][0] = -1e30f;
                if (c + 1 > rl)     s[ni][1] = -1e30f;
                if (c     > rl + 8) s[ni][2] = -1e30f;
                if (c + 1 > rl + 8) s[ni][3] = -1e30f;
            }
        }
        // ---- online softmax
        float mx0 = -1e30f, mx1 = -1e30f;
#pragma unroll
        for (int ni = 0; ni < 16; ni++) {
            mx0 = fmaxf(mx0, fmaxf(s[ni][0], s[ni][1]));
            mx1 = fmaxf(mx1, fmaxf(s[ni][2], s[ni][3]));
        }
        mx0 = fmaxf(mx0, __shfl_xor_sync(0xffffffffu, mx0, 1));
        mx0 = fmaxf(mx0, __shfl_xor_sync(0xffffffffu, mx0, 2));
        mx1 = fmaxf(mx1, __shfl_xor_sync(0xffffffffu, mx1, 1));
        mx1 = fmaxf(mx1, __shfl_xor_sync(0xffffffffu, mx1, 2));
        float mn0 = fmaxf(m0, mx0 * F), mn1 = fmaxf(m1, mx1 * F);
        float a0 = ex2f(m0 - mn0), a1 = ex2f(m1 - mn1);
        l0 *= a0; l1 *= a1;
#pragma unroll
        for (int ni = 0; ni < 8; ni++) {
            oacc[ni][0] *= a0; oacc[ni][1] *= a0;
            oacc[ni][2] *= a1; oacc[ni][3] *= a1;
        }
        m0 = mn0; m1 = mn1;

        uint32_t pa[16], pb[16], la[16], lb[16];
#pragma unroll
        for (int ni = 0; ni < 16; ni++) {
            float p0 = ex2f(fmaf(s[ni][0], F, -mn0));
            float p1 = ex2f(fmaf(s[ni][1], F, -mn0));
            float p2 = ex2f(fmaf(s[ni][2], F, -mn1));
            float p3 = ex2f(fmaf(s[ni][3], F, -mn1));
            l0 += p0 + p1; l1 += p2 + p3;
            uint32_t hA = packbf(p1, p0), hB = packbf(p3, p2);
            pa[ni] = hA; pb[ni] = hB;
            la[ni] = packbf(p1 - bfhi(hA), p0 - bflo(hA));
            lb[ni] = packbf(p3 - bfhi(hB), p2 - bflo(hB));
        }

        // ---- O += P V (bf16x3)
        {
            const uint32_t baseV = base + 16384u;
            int rv = (lane & 7) + ((lane >> 3) & 1) * 8;
#pragma unroll
            for (int ki = 0; ki < 8; ki++) {
                uint32_t ah[4] = {pa[2*ki], pb[2*ki], pa[2*ki+1], pb[2*ki+1]};
                uint32_t al[4] = {la[2*ki], lb[2*ki], la[2*ki+1], lb[2*ki+1]};
                int row = ki * 16 + rv;
#pragma unroll
                for (int dv = 0; dv < 4; dv++) {
                    int c8 = dv * 2 + ((lane >> 4) & 1);
                    uint32_t ad = baseV + row * 128 + (((c8 + (row & 7)) & 7) << 4);
                    uint32_t v0, v1, v2, v3, w0, w1, w2, w3;
                    LDM4T(v0, v1, v2, v3, ad);
                    LDM4T(w0, w1, w2, w3, ad + 16384u);
                    MMAB(oacc[2*dv],   ah, v0, v1);
                    MMAB(oacc[2*dv],   ah, w0, w1);
                    MMAB(oacc[2*dv],   al, v0, v1);
                    MMAB(oacc[2*dv+1], ah, v2, v3);
                    MMAB(oacc[2*dv+1], ah, w2, w3);
                    MMAB(oacc[2*dv+1], al, v2, v3);
                }
            }
        }
        if (lane == 0) mbar_arrive(fb + 32 + ((kb % 3) << 3));
    }

    // ---- epilogue: write O as fp16 in GEMM-A blocked layout
    l0 += __shfl_xor_sync(0xffffffffu, l0, 1);
    l0 += __shfl_xor_sync(0xffffffffu, l0, 2);
    l1 += __shfl_xor_sync(0xffffffffu, l1, 1);
    l1 += __shfl_xor_sync(0xffffffffu, l1, 2);
    const float i0 = 1.f / l0, i1 = 1.f / l1;
    const int rr0 = 16 * wid + g;
    const int rowg = b * 2048 + qb * 128 + rr0;
    const int rowBlk = rowg >> 7;
#pragma unroll
    for (int ni = 0; ni < 8; ni++) {
        int cg = h * 64 + ni * 8 + t4 * 2;
        int tile = rowBlk * 64 + (cg >> 5);
        int cc = cg & 31, ch = cc >> 3;
        __half2 h2a = __floats2half2_rn(oacc[ni][0] * i0, oacc[ni][1] * i0);
        __half2 h2b = __floats2half2_rn(oacc[ni][2] * i1, oacc[ni][3] * i1);
        int rr1 = rr0 + 8;
        size_t o0 = ((size_t)tile << 13) + rr0 * 64 + (((ch + (rr0 >> 1)) & 3) << 4) + (cc & 7) * 2;
        size_t o1 = ((size_t)tile << 13) + rr1 * 64 + (((ch + (rr1 >> 1)) & 3) << 4) + (cc & 7) * 2;
        *(__half2*)((char*)Oh + o0) = h2a;
        *(__half2*)((char*)Oh + o1) = h2b;
    }
}

// ---------------------------------------------------------------------------
extern "C" void kernel_launch(void* const* d_in, const int* in_sizes, int n_in,
                              void* d_out, int out_size) {
    const float* x  = (const float*)d_in[0];
    const float* wq = (const float*)d_in[1];
    const float* wk = (const float*)d_in[2];
    const float* wv = (const float*)d_in[3];
    const float* wo = (const float*)d_in[4];
    float* out = (float*)d_out;

    __nv_bfloat16 *xh, *xl, *wqh, *wql, *wkh, *wkl, *wvh, *wvl, *vh, *vl;
    __half *qh, *kh, *woh, *oh;
    cudaGetSymbolAddress((void**)&xh, g_xh);   cudaGetSymbolAddress((void**)&xl, g_xl);
    cudaGetSymbolAddress((void**)&wqh, g_wqh); cudaGetSymbolAddress((void**)&wql, g_wql);
    cudaGetSymbolAddress((void**)&wkh, g_wkh); cudaGetSymbolAddress((void**)&wkl, g_wkl);
    cudaGetSymbolAddress((void**)&wvh, g_wvh); cudaGetSymbolAddress((void**)&wvl, g_wvl);
    cudaGetSymbolAddress((void**)&vh, g_vh);   cudaGetSymbolAddress((void**)&vl, g_vl);
    cudaGetSymbolAddress((void**)&qh, g_qh);   cudaGetSymbolAddress((void**)&kh, g_kh);
    cudaGetSymbolAddress((void**)&woh, g_woh);
    cudaGetSymbolAddress((void**)&oh, g_oh);

    const int GSB = 4 * 49152 + 32;     // bf16x3 core smem
    const int GSH = HNST * 24576 + 40;  // fp16 core smem
    const int AS  = 163840 + 56;        // attn smem
    cudaFuncSetAttribute(gemm_qkv, cudaFuncAttributeMaxDynamicSharedMemorySize, GSB);
    cudaFuncSetAttribute(gemm_o,   cudaFuncAttributeMaxDynamicSharedMemorySize, GSH);
    cudaFuncSetAttribute(attn_mma, cudaFuncAttributeMaxDynamicSharedMemorySize, AS);

    SplitArgs sa;
    sa.src[0] = x;  sa.hi[0] = xh;  sa.lo[0] = xl;  sa.nchunk[0] = M_ * C_ / 8;
    sa.src[1] = wq; sa.hi[1] = wqh; sa.lo[1] = wql; sa.nchunk[1] = C_ * C_ / 8;
    sa.src[2] = wk; sa.hi[2] = wkh; sa.lo[2] = wkl; sa.nchunk[2] = KVC * C_ / 8;
    sa.src[3] = wv; sa.hi[3] = wvh; sa.lo[3] = wvl; sa.nchunk[3] = KVC * C_ / 8;
    split_all<<<dim3((M_ * C_ / 8 + 255) / 256, 4), 256>>>(sa);
    split_half<<<(C_ * C_ / 8 + 255) / 256, 256>>>(wo, woh, C_ * C_ / 8);

    gemm_qkv<<<dim3(24, 16), 256, GSB>>>(xh, xl, wqh, wql, wkh, wkl, wvh, wvl,
                                         qh, kh, vh, vl);
    attn_mma<<<dim3(T_ / 128, B_ * HQ), 256, AS>>>(qh, kh, vh, vl, oh);
    gemm_o<<<dim3(16, 16), 256, GSH>>>(oh, woh, out);
}